// round 1
// baseline (speedup 1.0000x reference)
#include <cuda_runtime.h>
#include <math.h>

static constexpr int BB = 65536;
static constexpr int DD = 64;
static constexpr int HH = 512;

// Scratch (allocation-free rule: __device__ globals)
__device__ float g_h0[(size_t)BB * HH];   // h0, later delta0
__device__ float g_h1[(size_t)BB * HH];   // h1, later delta1
__device__ float g_a [(size_t)BB * HH];   // delta2

// MODE 0: C = tanh(acc + bias[n])
// MODE 1: h = tanh(acc + bias[n]); C = w3[n] * (1 - h*h)
// MODE 2: g = gate[m*N+n];         C = acc * (1 - g*g)
// MODE 3: symplectic write of gradH into out[B, 64]
template<int BM, int BN, int BK, int TM, int TN, int MODE, bool TRANSB>
__global__ void __launch_bounds__((BM/TM)*(BN/TN))
gemm_fused(const float* __restrict__ A, const float* __restrict__ Bm,
           const float* __restrict__ bias, const float* __restrict__ w3,
           const float* __restrict__ gate, float* __restrict__ C,
           int M, int N, int K)
{
    constexpr int NTH = (BM/TM)*(BN/TN);
    __shared__ float As[BK][BM];
    __shared__ float Bs[BK][BN];

    const int bm = blockIdx.y * BM;
    const int bn = blockIdx.x * BN;
    const int tid = threadIdx.x;
    constexpr int TCOLS = BN / TN;
    const int tcol = tid % TCOLS;
    const int trow = tid / TCOLS;

    float acc[TM][TN];
#pragma unroll
    for (int i = 0; i < TM; i++)
#pragma unroll
        for (int j = 0; j < TN; j++) acc[i][j] = 0.f;

    constexpr int AV = (BM * BK) / 4;   // float4 loads for A tile
    constexpr int BV = (BN * BK) / 4;   // float4 loads for B tile
    constexpr int KV = BK / 4;          // float4 per K-row

    for (int k0 = 0; k0 < K; k0 += BK) {
        // ---- load A tile (row-major [M,K]) into As[k][m] ----
#pragma unroll
        for (int v = tid; v < AV; v += NTH) {
            int m   = v / KV;
            int kk4 = (v % KV) * 4;
            float4 t = *reinterpret_cast<const float4*>(
                &A[(size_t)(bm + m) * K + k0 + kk4]);
            As[kk4 + 0][m] = t.x;
            As[kk4 + 1][m] = t.y;
            As[kk4 + 2][m] = t.z;
            As[kk4 + 3][m] = t.w;
        }
        // ---- load B tile ----
        if (!TRANSB) {
            // B is [K, N] row-major; vectorize along N
#pragma unroll
            for (int v = tid; v < BV; v += NTH) {
                int r  = v / (BN / 4);
                int c4 = (v % (BN / 4)) * 4;
                float4 t = *reinterpret_cast<const float4*>(
                    &Bm[(size_t)(k0 + r) * N + bn + c4]);
                Bs[r][c4 + 0] = t.x;
                Bs[r][c4 + 1] = t.y;
                Bs[r][c4 + 2] = t.z;
                Bs[r][c4 + 3] = t.w;
            }
        } else {
            // B is [N, K] row-major (we need B^T); vectorize along K
#pragma unroll
            for (int v = tid; v < BV; v += NTH) {
                int n   = v / KV;
                int kk4 = (v % KV) * 4;
                float4 t = *reinterpret_cast<const float4*>(
                    &Bm[(size_t)(bn + n) * K + k0 + kk4]);
                Bs[kk4 + 0][n] = t.x;
                Bs[kk4 + 1][n] = t.y;
                Bs[kk4 + 2][n] = t.z;
                Bs[kk4 + 3][n] = t.w;
            }
        }
        __syncthreads();

#pragma unroll
        for (int kk = 0; kk < BK; kk++) {
            float ra[TM], rb[TN];
#pragma unroll
            for (int i = 0; i < TM; i++) ra[i] = As[kk][trow * TM + i];
#pragma unroll
            for (int j = 0; j < TN; j++) rb[j] = Bs[kk][tcol * TN + j];
#pragma unroll
            for (int i = 0; i < TM; i++)
#pragma unroll
                for (int j = 0; j < TN; j++)
                    acc[i][j] = fmaf(ra[i], rb[j], acc[i][j]);
        }
        __syncthreads();
    }

    // ---- fused epilogue ----
#pragma unroll
    for (int i = 0; i < TM; i++) {
        const int m = bm + trow * TM + i;
#pragma unroll
        for (int j = 0; j < TN; j++) {
            const int n = bn + tcol * TN + j;
            float v = acc[i][j];
            if (MODE == 0) {
                float h = tanhf(v + bias[n]);
                C[(size_t)m * N + n] = h;
            } else if (MODE == 1) {
                float h = tanhf(v + bias[n]);
                C[(size_t)m * N + n] = w3[n] * (1.f - h * h);
            } else if (MODE == 2) {
                float g = gate[(size_t)m * N + n];
                C[(size_t)m * N + n] = v * (1.f - g * g);
            } else { // MODE 3: out[:,0:32] = gradH[:,32:64]; out[:,32:64] = -gradH[:,0:32]
                if (n >= DD / 2) C[(size_t)m * DD + (n - DD / 2)] = v;
                else             C[(size_t)m * DD + (n + DD / 2)] = -v;
            }
        }
    }
}

extern "C" void kernel_launch(void* const* d_in, const int* in_sizes, int n_in,
                              void* d_out, int out_size)
{
    // metadata order: t, x, W0, b0, W1, b1, W2, b2, W3, b3
    const float* x  = (const float*)d_in[1];
    const float* W0 = (const float*)d_in[2];
    const float* b0 = (const float*)d_in[3];
    const float* W1 = (const float*)d_in[4];
    const float* b1 = (const float*)d_in[5];
    const float* W2 = (const float*)d_in[6];
    const float* b2 = (const float*)d_in[7];
    const float* W3 = (const float*)d_in[8];
    float* out = (float*)d_out;

    float *h0, *h1, *a;
    cudaGetSymbolAddress((void**)&h0, g_h0);
    cudaGetSymbolAddress((void**)&h1, g_h1);
    cudaGetSymbolAddress((void**)&a,  g_a);

    const dim3 blk(256);
    const dim3 grd_h(HH / 128, BB / 128);   // N=512 tiles
    const dim3 grd_o(1,        BB / 128);   // N=64 tile

    // 1) h0 = tanh(x @ W0 + b0)            [B,64]x[64,512]
    gemm_fused<128,128,8,8,8,0,false><<<grd_h, blk>>>(x,  W0, b0, nullptr, nullptr, h0, BB, HH, DD);
    // 2) h1 = tanh(h0 @ W1 + b1)           [B,512]x[512,512]
    gemm_fused<128,128,8,8,8,0,false><<<grd_h, blk>>>(h0, W1, b1, nullptr, nullptr, h1, BB, HH, HH);
    // 3) d2 = W3 * (1 - tanh^2(h1 @ W2 + b2))
    gemm_fused<128,128,8,8,8,1,false><<<grd_h, blk>>>(h1, W2, b2, W3,      nullptr, a,  BB, HH, HH);
    // 4) d1 = (d2 @ W2^T) * (1 - h1^2)   -> overwrite h1 (element-wise 1:1 with gate)
    gemm_fused<128,128,8,8,8,2,true ><<<grd_h, blk>>>(a,  W2, nullptr, nullptr, h1, h1, BB, HH, HH);
    // 5) d0 = (d1 @ W1^T) * (1 - h0^2)   -> overwrite h0
    gemm_fused<128,128,8,8,8,2,true ><<<grd_h, blk>>>(h1, W1, nullptr, nullptr, h0, h0, BB, HH, HH);
    // 6) out = symplectic(d0 @ W0^T)       [B,512]x[512,64]
    gemm_fused<128, 64,8,8,4,3,true ><<<grd_o, blk>>>(h0, W0, nullptr, nullptr, nullptr, out, BB, DD, HH);
}

// round 9
// speedup vs baseline: 3.6190x; 3.6190x over previous
#include <cuda_runtime.h>
#include <cuda_bf16.h>
#include <cstdint>
#include <math.h>

static constexpr int BB = 65536;
static constexpr int DD = 64;
static constexpr int HH = 512;

// ---------------- scratch (__device__ globals; allocation-free rule) -------------
__device__ __align__(16) __nv_bfloat16 g_xh[(size_t)BB * DD];
__device__ __align__(16) __nv_bfloat16 g_xl[(size_t)BB * DD];
__device__ __align__(16) __nv_bfloat16 g_h0h[(size_t)BB * HH];
__device__ __align__(16) __nv_bfloat16 g_h0l[(size_t)BB * HH];
__device__ __align__(16) __nv_bfloat16 g_h1h[(size_t)BB * HH];
__device__ __align__(16) __nv_bfloat16 g_h1l[(size_t)BB * HH];
__device__ __align__(16) __nv_bfloat16 g_dah[(size_t)BB * HH];   // d2, then reused for d0
__device__ __align__(16) __nv_bfloat16 g_dal[(size_t)BB * HH];
__device__ __align__(16) __nv_bfloat16 g_d1h[(size_t)BB * HH];
__device__ __align__(16) __nv_bfloat16 g_d1l[(size_t)BB * HH];
// Weight planes. Forward needs W^T ([N,K] K-major); backward needs W direct ([N,K]).
__device__ __align__(16) __nv_bfloat16 g_W0Th[HH * DD], g_W0Tl[HH * DD];   // [512,64]
__device__ __align__(16) __nv_bfloat16 g_W1Th[HH * HH], g_W1Tl[HH * HH];
__device__ __align__(16) __nv_bfloat16 g_W2Th[HH * HH], g_W2Tl[HH * HH];
__device__ __align__(16) __nv_bfloat16 g_W1h[HH * HH],  g_W1l[HH * HH];
__device__ __align__(16) __nv_bfloat16 g_W2h[HH * HH],  g_W2l[HH * HH];
__device__ __align__(16) __nv_bfloat16 g_W0h[DD * HH],  g_W0l[DD * HH];    // [64,512]

// ---------------- helpers (all base-target PTX: sm_80-era) ----------------
__device__ __forceinline__ uint32_t smem_u32(const void* p) {
    uint32_t a;
    asm("{ .reg .u64 t; cvta.to.shared.u64 t, %1; cvt.u32.u64 %0, t; }" : "=r"(a) : "l"(p));
    return a;
}
__device__ __forceinline__ void cp16(uint32_t s, const void* g) {
    asm volatile("cp.async.cg.shared.global [%0], [%1], 16;" :: "r"(s), "l"(g));
}
#define CP_COMMIT() asm volatile("cp.async.commit_group;" ::: "memory")
#define CP_WAIT1()  asm volatile("cp.async.wait_group 1;" ::: "memory")
#define CP_WAIT0()  asm volatile("cp.async.wait_group 0;" ::: "memory")

#define LDSM4(R, addr)                                                                   \
    asm volatile("ldmatrix.sync.aligned.m8n8.x4.shared.b16 {%0,%1,%2,%3}, [%4];"         \
        : "=r"((R)[0]), "=r"((R)[1]), "=r"((R)[2]), "=r"((R)[3]) : "r"(addr))

#define MMA16816(C, A, b0_, b1_)                                                         \
    asm volatile("mma.sync.aligned.m16n8k16.row.col.f32.bf16.bf16.f32 "                  \
        "{%0,%1,%2,%3},{%4,%5,%6,%7},{%8,%9},{%0,%1,%2,%3};"                             \
        : "+f"((C)[0]), "+f"((C)[1]), "+f"((C)[2]), "+f"((C)[3])                         \
        : "r"((A)[0]), "r"((A)[1]), "r"((A)[2]), "r"((A)[3]), "r"(b0_), "r"(b1_))

__device__ __forceinline__ float tanh_fast(float x) {
    float e = __expf(2.0f * x);
    return 1.0f - __fdividef(2.0f, e + 1.0f);
}
__device__ __forceinline__ float sech2_of(float z) {   // 1 - tanh(z)^2
    float e = __expf(2.0f * z);
    float s = __fdividef(2.0f, e + 1.0f);              // s = 1 - tanh
    return s * (2.0f - s);
}
__device__ __forceinline__ void split2(float a, float b, uint32_t& hi, uint32_t& lo) {
    __nv_bfloat16 ah = __float2bfloat16(a), bh = __float2bfloat16(b);
    float ar = a - __bfloat162float(ah), br = b - __bfloat162float(bh);
    __nv_bfloat16 al = __float2bfloat16(ar), bl = __float2bfloat16(br);
    hi = (uint32_t)__bfloat16_as_ushort(ah) | ((uint32_t)__bfloat16_as_ushort(bh) << 16);
    lo = (uint32_t)__bfloat16_as_ushort(al) | ((uint32_t)__bfloat16_as_ushort(bl) << 16);
}
__device__ __forceinline__ float bflo(uint32_t u) {
    return __bfloat162float(__ushort_as_bfloat16((unsigned short)(u & 0xFFFF)));
}
__device__ __forceinline__ float bfhi(uint32_t u) {
    return __bfloat162float(__ushort_as_bfloat16((unsigned short)(u >> 16)));
}

// ---------------- prep kernels: fp32 -> (hi,lo) bf16 planes ----------------
__global__ void split_direct(const float* __restrict__ src, __nv_bfloat16* __restrict__ hi,
                             __nv_bfloat16* __restrict__ lo, int n) {
    int i = blockIdx.x * blockDim.x + threadIdx.x;
    if (i < n) {
        float v = src[i];
        __nv_bfloat16 h = __float2bfloat16(v);
        hi[i] = h;
        lo[i] = __float2bfloat16(v - __bfloat162float(h));
    }
}
__global__ void split_trans(const float* __restrict__ src, __nv_bfloat16* __restrict__ hi,
                            __nv_bfloat16* __restrict__ lo, int R, int C) {
    int i = blockIdx.x * blockDim.x + threadIdx.x;
    if (i < R * C) {
        int r = i / C, c = i % C;
        float v = src[i];
        __nv_bfloat16 h = __float2bfloat16(v);
        hi[(size_t)c * R + r] = h;
        lo[(size_t)c * R + r] = __float2bfloat16(v - __bfloat162float(h));
    }
}

// ---------------- stage loader: global -> padded smem via cp.async ----------------
// Smem rows: 32 bf16 data (64B) padded to 80B (20 words -> conflict-free ldmatrix).
template<int BN>
__device__ __forceinline__ void load_stage(
    uint32_t base_u, int buf,
    const __nv_bfloat16* __restrict__ Ah, const __nv_bfloat16* __restrict__ Al,
    const __nv_bfloat16* __restrict__ Bh, const __nv_bfloat16* __restrict__ Bl,
    int bm, int bn, int K, int k0, int tid)
{
    constexpr int ASZ = 128 * 80;
    constexpr int BSZ = BN * 80;
    constexpr int STAGE = 2 * ASZ + 2 * BSZ;
    uint32_t sb = base_u + (uint32_t)(buf * STAGE);
#pragma unroll
    for (int i = tid; i < 128 * 4; i += 256) {
        int r = i >> 2, cc = i & 3;
        size_t go = (size_t)(bm + r) * K + k0 + cc * 8;
        uint32_t so = sb + (uint32_t)(r * 80 + cc * 16);
        cp16(so, Ah + go);
        cp16(so + ASZ, Al + go);
    }
#pragma unroll
    for (int i = tid; i < BN * 4; i += 256) {
        int r = i >> 2, cc = i & 3;
        size_t go = (size_t)(bn + r) * K + k0 + cc * 8;
        uint32_t so = sb + (uint32_t)(2 * ASZ + r * 80 + cc * 16);
        cp16(so, Bh + go);
        cp16(so + BSZ, Bl + go);
    }
}

// ---------------- fused split-bf16 HMMA GEMM ----------------
// C[m,n] = sum_k A[m,k]*B[n,k];  A ~ Ah+Al, B ~ Bh+Bl (drop Al*Bl).
// MODE 0: h = tanh(v + bias[n])                 -> (Oh,Ol)
// MODE 1: out = w3[n]*(1 - tanh^2(v+bias[n]))   -> (Oh,Ol)
// MODE 2: g = Gh+Gl;  out = v*(1-g^2)           -> (Oh,Ol)
// MODE 3: symplectic fp32 write                 -> Of [B,64]
template<int MODE, int BN, int WARPS_M>
__global__ void __launch_bounds__(256)
hnn_mma(const __nv_bfloat16* __restrict__ Ah, const __nv_bfloat16* __restrict__ Al,
        const __nv_bfloat16* __restrict__ Bh, const __nv_bfloat16* __restrict__ Bl,
        const float* __restrict__ bias, const float* __restrict__ w3,
        const __nv_bfloat16* __restrict__ Gh, const __nv_bfloat16* __restrict__ Gl,
        __nv_bfloat16* __restrict__ Oh, __nv_bfloat16* __restrict__ Ol,
        float* __restrict__ Of, int K)
{
    constexpr int WARPS_N = 8 / WARPS_M;
    constexpr int WM = 128 / WARPS_M;          // 32 (BN=128) or 16 (BN=64)
    constexpr int WN = BN / WARPS_N;           // 64
    constexpr int MI = WM / 16;                // 2 or 1
    constexpr int NI = WN / 8;                 // 8
    constexpr int ASZ = 128 * 80;
    constexpr int BSZ = BN * 80;
    constexpr int STAGE = 2 * ASZ + 2 * BSZ;

    extern __shared__ char sm[];
    const uint32_t base_u = smem_u32(sm);
    const int tid = threadIdx.x;
    const int lane = tid & 31;
    const int wid = tid >> 5;
    const int wm = wid % WARPS_M;
    const int wn = wid / WARPS_M;
    const int bm = blockIdx.y * 128;
    const int bn = blockIdx.x * BN;
    const int NK = K >> 5;

    float acc[MI][NI][4];
#pragma unroll
    for (int mi = 0; mi < MI; mi++)
#pragma unroll
        for (int ni = 0; ni < NI; ni++)
#pragma unroll
            for (int r = 0; r < 4; r++) acc[mi][ni][r] = 0.0f;

    load_stage<BN>(base_u, 0, Ah, Al, Bh, Bl, bm, bn, K, 0, tid);
    CP_COMMIT();

    for (int ks = 0; ks < NK; ks++) {
        if (ks + 1 < NK) {
            load_stage<BN>(base_u, (ks + 1) & 1, Ah, Al, Bh, Bl, bm, bn, K, (ks + 1) << 5, tid);
            CP_COMMIT();
            CP_WAIT1();
        } else {
            CP_WAIT0();
        }
        __syncthreads();

        const uint32_t sb = base_u + (uint32_t)((ks & 1) * STAGE);
#pragma unroll
        for (int kk = 0; kk < 2; kk++) {
            const int kb = kk * 16;
            uint32_t afh[MI][4], afl[MI][4];
#pragma unroll
            for (int mi = 0; mi < MI; mi++) {
                uint32_t addr = sb + (uint32_t)((wm * WM + mi * 16 + (lane & 15)) * 80 +
                                                (kb + (lane >> 4) * 8) * 2);
                LDSM4(afh[mi], addr);
                LDSM4(afl[mi], addr + ASZ);
            }
#pragma unroll
            for (int n2 = 0; n2 < NI / 2; n2++) {
                uint32_t baddr = sb + (uint32_t)(2 * ASZ +
                    (wn * WN + n2 * 16 + ((lane >> 4) << 3) + (lane & 7)) * 80 +
                    (kb + ((lane >> 3) & 1) * 8) * 2);
                uint32_t bfh[4], bfl[4];
                LDSM4(bfh, baddr);
                LDSM4(bfl, baddr + BSZ);
#pragma unroll
                for (int mi = 0; mi < MI; mi++) {
                    MMA16816(acc[mi][2 * n2],     afh[mi], bfh[0], bfh[1]);
                    MMA16816(acc[mi][2 * n2 + 1], afh[mi], bfh[2], bfh[3]);
                    MMA16816(acc[mi][2 * n2],     afh[mi], bfl[0], bfl[1]);
                    MMA16816(acc[mi][2 * n2 + 1], afh[mi], bfl[2], bfl[3]);
                    MMA16816(acc[mi][2 * n2],     afl[mi], bfh[0], bfh[1]);
                    MMA16816(acc[mi][2 * n2 + 1], afl[mi], bfh[2], bfh[3]);
                }
            }
        }
        __syncthreads();
    }

    // -------- fused epilogue --------
#pragma unroll
    for (int mi = 0; mi < MI; mi++) {
#pragma unroll
        for (int ni = 0; ni < NI; ni++) {
            float c0 = acc[mi][ni][0], c1 = acc[mi][ni][1];
            float c2 = acc[mi][ni][2], c3 = acc[mi][ni][3];
            const int gn = bn + wn * WN + ni * 8 + (lane & 3) * 2;
            const int r0 = bm + wm * WM + mi * 16 + (lane >> 2);
            const int r1 = r0 + 8;

            if (MODE == 0 || MODE == 1) {
                const float bb0 = bias[gn], bb1 = bias[gn + 1];
                float v0, v1, v2, v3;
                if (MODE == 0) {
                    v0 = tanh_fast(c0 + bb0); v1 = tanh_fast(c1 + bb1);
                    v2 = tanh_fast(c2 + bb0); v3 = tanh_fast(c3 + bb1);
                } else {
                    const float w0 = w3[gn], w1 = w3[gn + 1];
                    v0 = w0 * sech2_of(c0 + bb0); v1 = w1 * sech2_of(c1 + bb1);
                    v2 = w0 * sech2_of(c2 + bb0); v3 = w1 * sech2_of(c3 + bb1);
                }
                uint32_t hi, lo;
                split2(v0, v1, hi, lo);
                *reinterpret_cast<uint32_t*>(Oh + (size_t)r0 * HH + gn) = hi;
                *reinterpret_cast<uint32_t*>(Ol + (size_t)r0 * HH + gn) = lo;
                split2(v2, v3, hi, lo);
                *reinterpret_cast<uint32_t*>(Oh + (size_t)r1 * HH + gn) = hi;
                *reinterpret_cast<uint32_t*>(Ol + (size_t)r1 * HH + gn) = lo;
            } else if (MODE == 2) {
                uint32_t gh0 = *reinterpret_cast<const uint32_t*>(Gh + (size_t)r0 * HH + gn);
                uint32_t gl0 = *reinterpret_cast<const uint32_t*>(Gl + (size_t)r0 * HH + gn);
                uint32_t gh1 = *reinterpret_cast<const uint32_t*>(Gh + (size_t)r1 * HH + gn);
                uint32_t gl1 = *reinterpret_cast<const uint32_t*>(Gl + (size_t)r1 * HH + gn);
                float ga = bflo(gh0) + bflo(gl0), gb = bfhi(gh0) + bfhi(gl0);
                float gc = bflo(gh1) + bflo(gl1), gd = bfhi(gh1) + bfhi(gl1);
                float v0 = c0 * (1.0f - ga * ga), v1 = c1 * (1.0f - gb * gb);
                float v2 = c2 * (1.0f - gc * gc), v3 = c3 * (1.0f - gd * gd);
                uint32_t hi, lo;
                split2(v0, v1, hi, lo);
                *reinterpret_cast<uint32_t*>(Oh + (size_t)r0 * HH + gn) = hi;
                *reinterpret_cast<uint32_t*>(Ol + (size_t)r0 * HH + gn) = lo;
                split2(v2, v3, hi, lo);
                *reinterpret_cast<uint32_t*>(Oh + (size_t)r1 * HH + gn) = hi;
                *reinterpret_cast<uint32_t*>(Ol + (size_t)r1 * HH + gn) = lo;
            } else { // MODE 3: out[:,0:32] = grad[:,32:64]; out[:,32:64] = -grad[:,0:32]
                const int dc = (gn >= 32) ? gn - 32 : gn + 32;
                const float sgn = (gn >= 32) ? 1.0f : -1.0f;
                float2 t0; t0.x = sgn * c0; t0.y = sgn * c1;
                float2 t1; t1.x = sgn * c2; t1.y = sgn * c3;
                *reinterpret_cast<float2*>(Of + (size_t)r0 * DD + dc) = t0;
                *reinterpret_cast<float2*>(Of + (size_t)r1 * DD + dc) = t1;
            }
        }
    }
}

// ---------------- host ----------------
extern "C" void kernel_launch(void* const* d_in, const int* in_sizes, int n_in,
                              void* d_out, int out_size)
{
    const float* x  = (const float*)d_in[1];
    const float* W0 = (const float*)d_in[2];
    const float* b0 = (const float*)d_in[3];
    const float* W1 = (const float*)d_in[4];
    const float* b1 = (const float*)d_in[5];
    const float* W2 = (const float*)d_in[6];
    const float* b2 = (const float*)d_in[7];
    const float* W3 = (const float*)d_in[8];
    float* out = (float*)d_out;

    __nv_bfloat16 *xh, *xl, *h0h, *h0l, *h1h, *h1l, *dah, *dal, *d1h, *d1l;
    __nv_bfloat16 *W0Th, *W0Tl, *W1Th, *W1Tl, *W2Th, *W2Tl, *W1h, *W1l, *W2h, *W2l, *W0h, *W0l;
    cudaGetSymbolAddress((void**)&xh,  g_xh);   cudaGetSymbolAddress((void**)&xl,  g_xl);
    cudaGetSymbolAddress((void**)&h0h, g_h0h);  cudaGetSymbolAddress((void**)&h0l, g_h0l);
    cudaGetSymbolAddress((void**)&h1h, g_h1h);  cudaGetSymbolAddress((void**)&h1l, g_h1l);
    cudaGetSymbolAddress((void**)&dah, g_dah);  cudaGetSymbolAddress((void**)&dal, g_dal);
    cudaGetSymbolAddress((void**)&d1h, g_d1h);  cudaGetSymbolAddress((void**)&d1l, g_d1l);
    cudaGetSymbolAddress((void**)&W0Th, g_W0Th); cudaGetSymbolAddress((void**)&W0Tl, g_W0Tl);
    cudaGetSymbolAddress((void**)&W1Th, g_W1Th); cudaGetSymbolAddress((void**)&W1Tl, g_W1Tl);
    cudaGetSymbolAddress((void**)&W2Th, g_W2Th); cudaGetSymbolAddress((void**)&W2Tl, g_W2Tl);
    cudaGetSymbolAddress((void**)&W1h,  g_W1h);  cudaGetSymbolAddress((void**)&W1l,  g_W1l);
    cudaGetSymbolAddress((void**)&W2h,  g_W2h);  cudaGetSymbolAddress((void**)&W2l,  g_W2l);
    cudaGetSymbolAddress((void**)&W0h,  g_W0h);  cudaGetSymbolAddress((void**)&W0l,  g_W0l);

    // Stage bytes: 2 A planes (128*80) + 2 B planes (BN*80); double-buffered.
    constexpr int SM128 = 2 * (2 * 128 * 80 + 2 * 128 * 80);   // 81920
    constexpr int SM64  = 2 * (2 * 128 * 80 + 2 * 64 * 80);    // 61440
    cudaFuncSetAttribute(hnn_mma<0, 128, 4>, cudaFuncAttributeMaxDynamicSharedMemorySize, SM128);
    cudaFuncSetAttribute(hnn_mma<1, 128, 4>, cudaFuncAttributeMaxDynamicSharedMemorySize, SM128);
    cudaFuncSetAttribute(hnn_mma<2, 128, 4>, cudaFuncAttributeMaxDynamicSharedMemorySize, SM128);
    cudaFuncSetAttribute(hnn_mma<3, 64, 8>,  cudaFuncAttributeMaxDynamicSharedMemorySize, SM64);

    // ---- prep: split/transpose operands into bf16 planes ----
    {
        int n;
        n = BB * DD; split_direct<<<(n + 255) / 256, 256>>>(x, xh, xl, n);
        n = DD * HH; split_direct<<<(n + 255) / 256, 256>>>(W0, W0h, W0l, n);
        split_trans<<<(n + 255) / 256, 256>>>(W0, W0Th, W0Tl, DD, HH);
        n = HH * HH;
        split_direct<<<(n + 255) / 256, 256>>>(W1, W1h, W1l, n);
        split_direct<<<(n + 255) / 256, 256>>>(W2, W2h, W2l, n);
        split_trans<<<(n + 255) / 256, 256>>>(W1, W1Th, W1Tl, HH, HH);
        split_trans<<<(n + 255) / 256, 256>>>(W2, W2Th, W2Tl, HH, HH);
    }

    const dim3 gH(HH / 128, BB / 128);   // (4, 512)
    const dim3 gO(1,        BB / 128);   // (1, 512)

    // 1) h0 = tanh(x @ W0 + b0)
    hnn_mma<0, 128, 4><<<gH, 256, SM128>>>(xh, xl, W0Th, W0Tl, b0, nullptr, nullptr, nullptr,
                                           h0h, h0l, nullptr, DD);
    // 2) h1 = tanh(h0 @ W1 + b1)
    hnn_mma<0, 128, 4><<<gH, 256, SM128>>>(h0h, h0l, W1Th, W1Tl, b1, nullptr, nullptr, nullptr,
                                           h1h, h1l, nullptr, HH);
    // 3) d2 = W3 * (1 - tanh^2(h1 @ W2 + b2))
    hnn_mma<1, 128, 4><<<gH, 256, SM128>>>(h1h, h1l, W2Th, W2Tl, b2, W3, nullptr, nullptr,
                                           dah, dal, nullptr, HH);
    // 4) d1 = (d2 @ W2^T) * (1 - h1^2)
    hnn_mma<2, 128, 4><<<gH, 256, SM128>>>(dah, dal, W2h, W2l, nullptr, nullptr, h1h, h1l,
                                           d1h, d1l, nullptr, HH);
    // 5) d0 = (d1 @ W1^T) * (1 - h0^2)   (reuse da buffers)
    hnn_mma<2, 128, 4><<<gH, 256, SM128>>>(d1h, d1l, W1h, W1l, nullptr, nullptr, h0h, h0l,
                                           dah, dal, nullptr, HH);
    // 6) out = symplectic(d0 @ W0^T)
    hnn_mma<3, 64, 8><<<gO, 256, SM64>>>(dah, dal, W0h, W0l, nullptr, nullptr, nullptr, nullptr,
                                         nullptr, nullptr, out, HH);
}